// round 12
// baseline (speedup 1.0000x reference)
#include <cuda_runtime.h>
#include <cuda_bf16.h>
#include <math.h>
#include <cstdint>

// Problem constants (GCNAggregator): B=4096, K=32, U=32768, V=100000, D=128
#define GCN_B 4096
#define GCN_K 32
#define GCN_U 32768
#define GCN_D 128

#define AGG_WARPS 4            // rows (warps) per aggregate block
#define KBULK 16               // neighbors fetched via cp.async.bulk (staged)
#define KLDG  (GCN_K - KBULK)  // neighbors fetched via rolling LDG pipeline
#define STAGE_PER_WARP (KBULK * 512)   // 8KB

// Scratch (no cudaMalloc allowed)
__device__ int g_col_deg[GCN_U];

// ---------------------------------------------------------------------------
// Kernel 1: per-row dedupe (one warp per row) + column degree accumulation.
// ---------------------------------------------------------------------------
__global__ void dedupe_degree_kernel(const int* __restrict__ neigh_cols) {
    int warp_in_block = threadIdx.x >> 5;
    int lane = threadIdx.x & 31;
    int b = blockIdx.x * (blockDim.x >> 5) + warp_in_block;

    int c = neigh_cols[b * GCN_K + lane];
    unsigned peers = __match_any_sync(0xFFFFFFFFu, c);
    bool first = ((int)__ffs(peers) - 1) == lane;   // lowest lane holding c
    if (first) atomicAdd(&g_col_deg[c], 1);         // spread addresses -> cheap
}

// ---------------------------------------------------------------------------
// mbarrier helpers
// ---------------------------------------------------------------------------
__device__ __forceinline__ void mbar_init(unsigned mbar, unsigned count) {
    asm volatile("mbarrier.init.shared.b64 [%0], %1;" :: "r"(mbar), "r"(count) : "memory");
}
__device__ __forceinline__ void mbar_expect_tx(unsigned mbar, unsigned bytes) {
    asm volatile("mbarrier.arrive.expect_tx.shared.b64 _, [%0], %1;"
                 :: "r"(mbar), "r"(bytes) : "memory");
}
__device__ __forceinline__ void mbar_wait(unsigned mbar, unsigned parity) {
    asm volatile(
        "{\n\t"
        ".reg .pred P;\n\t"
        "WAIT_%=:\n\t"
        "mbarrier.try_wait.parity.acquire.cta.shared::cta.b64 P, [%0], %1, 0x989680;\n\t"
        "@P bra.uni DONE_%=;\n\t"
        "bra.uni WAIT_%=;\n\t"
        "DONE_%=:\n\t"
        "}"
        :: "r"(mbar), "r"(parity) : "memory");
}

// ---------------------------------------------------------------------------
// Kernel 2: hybrid-engine aggregation. One warp per row.
//   - Neighbors [KLDG, 32): ALL issued immediately via cp.async.bulk (512B
//     each, lanes 0..15) into an 8KB/warp smem stage -> bulk/TMA engine,
//     which is NOT behind the per-SM L1tex outstanding-line cap.
//   - Neighbors [0, KLDG): depth-8 rolling __ldcg pipeline -> LDG engine.
//   Both queues drain concurrently; the weight chain (match_any dedupe +
//   degree load + rsqrt) resolves under the in-flight loads. One mbarrier
//   wait at the end, then FMA the staged half. Duplicates carry w=0.
// ---------------------------------------------------------------------------
__global__ void __launch_bounds__(32 * AGG_WARPS)
aggregate_kernel(const int* __restrict__ neigh_cols,
                 const int* __restrict__ unique_ids,
                 const float4* __restrict__ embed_table4,  // [V, 32] float4
                 float4* __restrict__ out4) {              // [B, 32] float4
    __shared__ float4 s_stage[AGG_WARPS][KBULK][32];       // 32KB
    __shared__ int    s_off[AGG_WARPS][GCN_K];
    __shared__ float  s_w[AGG_WARPS][GCN_K];
    __shared__ alignas(8) uint64_t s_mbar[AGG_WARPS];

    const int tid  = threadIdx.x;
    const int warp = tid >> 5;
    const int lane = tid & 31;
    const int b    = blockIdx.x * AGG_WARPS + warp;

    if (tid < AGG_WARPS) {
        mbar_init((unsigned)__cvta_generic_to_shared(&s_mbar[tid]), 1);
    }
    __syncthreads();
    if (tid < AGG_WARPS) {
        asm volatile("fence.proxy.async.shared::cta;" ::: "memory");
    }

    // ---- step 1: offsets first (shortest chain), publish to warp-private smem ----
    const int c = neigh_cols[b * GCN_K + lane];
    const int off4 = __ldg(&unique_ids[c]) * (GCN_D / 4);
    s_off[warp][lane] = off4;
    __syncwarp();

    const unsigned mbar = (unsigned)__cvta_generic_to_shared(&s_mbar[warp]);
    const unsigned stage = (unsigned)__cvta_generic_to_shared(&s_stage[warp][0][0]);

    // ---- step 2a: fire ALL bulk copies for neighbors [KLDG, 32) ----
    if (lane == 0) mbar_expect_tx(mbar, STAGE_PER_WARP);
    if (lane < KBULK) {
        const float4* src = embed_table4 + s_off[warp][KLDG + lane];
        unsigned dst = stage + (unsigned)(lane * 512);
        asm volatile(
            "cp.async.bulk.shared::cluster.global.mbarrier::complete_tx::bytes "
            "[%0], [%1], %2, [%3];"
            :: "r"(dst), "l"(src), "n"(512), "r"(mbar)
            : "memory");
    }

    // ---- step 2b: launch the LDG rolling pipeline for neighbors [0, KLDG) ----
    constexpr int P = 8;
    float4 buf[P];
    #pragma unroll
    for (int i = 0; i < P; i++)
        buf[i] = __ldcg(&embed_table4[s_off[warp][i] + lane]);

    // ---- step 3: weight chain resolves under the in-flight loads ----
    unsigned peers = __match_any_sync(0xFFFFFFFFu, c);
    bool first = ((int)__ffs(peers) - 1) == lane;
    unsigned mask = __ballot_sync(0xFFFFFFFFu, first);
    float w = 0.0f;
    if (first) {
        int deg = __ldcg(&g_col_deg[c]);            // >= 1 for first occurrences
        w = rsqrtf((float)deg);
    }
    w *= rsqrtf((float)__popc(mask));               // fold row scale into lane weight
    s_w[warp][lane] = w;
    __syncwarp();

    // ---- step 4: FMA + refill over the LDG half ----
    float4 acc = make_float4(0.f, 0.f, 0.f, 0.f);
    #pragma unroll
    for (int k = 0; k < KLDG; k++) {
        float4 v  = buf[k & (P - 1)];
        float  wk = s_w[warp][k];
        acc.x = fmaf(wk, v.x, acc.x);
        acc.y = fmaf(wk, v.y, acc.y);
        acc.z = fmaf(wk, v.z, acc.z);
        acc.w = fmaf(wk, v.w, acc.w);
        if (k + P < KLDG)
            buf[k & (P - 1)] = __ldcg(&embed_table4[s_off[warp][k + P] + lane]);
    }

    // ---- step 5: bulk half is (long since) landed -> FMA from smem ----
    mbar_wait(mbar, 0);
    #pragma unroll
    for (int k = 0; k < KBULK; k++) {
        float  wk = s_w[warp][KLDG + k];
        float4 v  = s_stage[warp][k][lane];
        acc.x = fmaf(wk, v.x, acc.x);
        acc.y = fmaf(wk, v.y, acc.y);
        acc.z = fmaf(wk, v.z, acc.z);
        acc.w = fmaf(wk, v.w, acc.w);
    }

    out4[b * (GCN_D / 4) + lane] = acc;
}

// ---------------------------------------------------------------------------
extern "C" void kernel_launch(void* const* d_in, const int* in_sizes, int n_in,
                              void* d_out, int out_size) {
    const int*    neigh_cols   = (const int*)d_in[0];
    const int*    unique_ids   = (const int*)d_in[1];
    const float4* embed_table4 = (const float4*)d_in[2];
    float4*       out4         = (float4*)d_out;

    // Zero column degrees via a graph memset node (no dedicated kernel launch).
    void* col_deg_ptr = nullptr;
    cudaGetSymbolAddress(&col_deg_ptr, g_col_deg);
    cudaMemsetAsync(col_deg_ptr, 0, GCN_U * sizeof(int));

    dedupe_degree_kernel<<<GCN_B / 8, 256>>>(neigh_cols);
    aggregate_kernel<<<GCN_B / AGG_WARPS, 32 * AGG_WARPS>>>(
        neigh_cols, unique_ids, embed_table4, out4);
}

// round 13
// speedup vs baseline: 1.1359x; 1.1359x over previous
#include <cuda_runtime.h>
#include <cuda_bf16.h>
#include <math.h>
#include <cstdint>

// Problem constants (GCNAggregator): B=4096, K=32, U=32768, V=100000, D=128
#define GCN_B 4096
#define GCN_K 32
#define GCN_U 32768
#define GCN_D 128
#define AGG_WARPS 8      // rows (warps) per aggregate block

// Scratch (no cudaMalloc allowed)
__device__ int g_col_deg[GCN_U];

// ---------------------------------------------------------------------------
// Kernel 1: per-row dedupe (one warp per row) + column degree accumulation.
// match_any: one instruction instead of a 32-step shfl chain.
// ---------------------------------------------------------------------------
__global__ void dedupe_degree_kernel(const int* __restrict__ neigh_cols) {
    int warp_in_block = threadIdx.x >> 5;
    int lane = threadIdx.x & 31;
    int b = blockIdx.x * (blockDim.x >> 5) + warp_in_block;

    int c = neigh_cols[b * GCN_K + lane];
    unsigned peers = __match_any_sync(0xFFFFFFFFu, c);
    bool first = ((int)__ffs(peers) - 1) == lane;   // lowest lane holding c
    if (first) atomicAdd(&g_col_deg[c], 1);         // spread addresses -> cheap
}

// ---------------------------------------------------------------------------
// Kernel 2: aggregation (champion structure, R10 + micro-opts).
// One warp per row; lane owns 4 consecutive dims (LDG.128 via __ldcg).
// Offsets resolve first and the gather pipeline launches immediately; the
// weight chain (match_any dedupe + degree load + rsqrt) executes under the
// first 8 in-flight gathers and is only consumed at FMA time. (off, w)
// packed as int2 -> one LDS.64 per k. Duplicates carry w=0 -> branch-free.
// ---------------------------------------------------------------------------
__global__ void __launch_bounds__(32 * AGG_WARPS)
aggregate_kernel(const int* __restrict__ neigh_cols,
                 const int* __restrict__ unique_ids,
                 const float4* __restrict__ embed_table4,  // [V, 32] float4
                 float4* __restrict__ out4) {              // [B, 32] float4
    const int warp = threadIdx.x >> 5;
    const int lane = threadIdx.x & 31;
    const int b    = blockIdx.x * AGG_WARPS + warp;

    __shared__ int2 s_wo[AGG_WARPS][GCN_K];   // {off4, bitcast(w)}

    // ---- step 1: offsets only (shortest chain), publish to warp-private smem ----
    const int c = neigh_cols[b * GCN_K + lane];
    const int off4 = __ldg(&unique_ids[c]) * (GCN_D / 4);
    s_wo[warp][lane].x = off4;
    __syncwarp();

    // ---- step 2: launch the gather pipeline immediately ----
    constexpr int P = 8;
    float4 buf[P];
    #pragma unroll
    for (int i = 0; i < P; i++)
        buf[i] = __ldcg(&embed_table4[s_wo[warp][i].x + lane]);

    // ---- step 3: weight chain resolves under the in-flight gathers ----
    unsigned peers = __match_any_sync(0xFFFFFFFFu, c);
    bool first = ((int)__ffs(peers) - 1) == lane;
    unsigned mask = __ballot_sync(0xFFFFFFFFu, first);
    float w = 0.0f;
    if (first) {
        int deg = __ldcg(&g_col_deg[c]);            // >= 1 for first occurrences
        w = rsqrtf((float)deg);
    }
    w *= rsqrtf((float)__popc(mask));               // fold row scale into lane weight
    s_wo[warp][lane].y = __float_as_int(w);
    __syncwarp();

    // ---- step 4: rolling FMA + refill ----
    float4 acc = make_float4(0.f, 0.f, 0.f, 0.f);
    #pragma unroll
    for (int k = 0; k < GCN_K; k++) {
        int2  wo = s_wo[warp][k];
        float wk = __int_as_float(wo.y);
        float4 v = buf[k & (P - 1)];
        acc.x = fmaf(wk, v.x, acc.x);
        acc.y = fmaf(wk, v.y, acc.y);
        acc.z = fmaf(wk, v.z, acc.z);
        acc.w = fmaf(wk, v.w, acc.w);
        if (k + P < GCN_K)
            buf[k & (P - 1)] = __ldcg(&embed_table4[s_wo[warp][k + P].x + lane]);
    }

    out4[b * (GCN_D / 4) + lane] = acc;
}

// ---------------------------------------------------------------------------
extern "C" void kernel_launch(void* const* d_in, const int* in_sizes, int n_in,
                              void* d_out, int out_size) {
    const int*    neigh_cols   = (const int*)d_in[0];
    const int*    unique_ids   = (const int*)d_in[1];
    const float4* embed_table4 = (const float4*)d_in[2];
    float4*       out4         = (float4*)d_out;

    // Zero column degrees via a graph memset node (no dedicated kernel launch).
    void* col_deg_ptr = nullptr;
    cudaGetSymbolAddress(&col_deg_ptr, g_col_deg);
    cudaMemsetAsync(col_deg_ptr, 0, GCN_U * sizeof(int));

    dedupe_degree_kernel<<<GCN_B / 8, 256>>>(neigh_cols);
    aggregate_kernel<<<GCN_B / AGG_WARPS, 32 * AGG_WARPS>>>(
        neigh_cols, unique_ids, embed_table4, out4);
}

// round 15
// speedup vs baseline: 1.1555x; 1.0173x over previous
#include <cuda_runtime.h>
#include <cuda_bf16.h>
#include <math.h>
#include <cstdint>

// Problem constants (GCNAggregator): B=4096, K=32, U=32768, V=100000, D=128
#define GCN_B 4096
#define GCN_K 32
#define GCN_U 32768
#define GCN_D 128
#define AGG_WARPS 4      // rows (warps) per aggregate block -> 1024 blocks

// Scratch (no cudaMalloc allowed)
__device__ int  g_col_deg[GCN_U];
__device__ int2 g_oc[GCN_B * GCN_K];   // per edge: {off4, c | (first << 31)}

// ---------------------------------------------------------------------------
// Kernel 1: per-row dedupe + degree accumulation + edge precompute.
// Resolves the unique_ids indirection HERE (latency-hidden; this kernel is
// far from any throughput limit) so the aggregate prologue needs only one
// LDG.64 before its gathers can launch.
// ---------------------------------------------------------------------------
__global__ void dedupe_degree_kernel(const int* __restrict__ neigh_cols,
                                     const int* __restrict__ unique_ids) {
    int warp_in_block = threadIdx.x >> 5;
    int lane = threadIdx.x & 31;
    int b = blockIdx.x * (blockDim.x >> 5) + warp_in_block;
    int e = b * GCN_K + lane;

    int c = neigh_cols[e];
    int off4 = __ldg(&unique_ids[c]) * (GCN_D / 4);   // independent -> hidden

    unsigned peers = __match_any_sync(0xFFFFFFFFu, c);
    bool first = ((int)__ffs(peers) - 1) == lane;     // lowest lane holding c
    if (first) atomicAdd(&g_col_deg[c], 1);           // spread addresses -> cheap

    g_oc[e] = make_int2(off4, c | (first ? 0x80000000 : 0));
}

// ---------------------------------------------------------------------------
// Kernel 2: aggregation. One warp per row; lane owns 4 consecutive dims
// (LDG.128 via __ldcg). Prologue is a single LDG.64 of the precomputed
// (off4, flagged c): gathers launch after ONE memory epoch. Weight chain
// (ballot + degree load + rsqrt) resolves under the in-flight gathers.
// Duplicates carry w=0 -> branch-free.
// ---------------------------------------------------------------------------
__global__ void __launch_bounds__(32 * AGG_WARPS)
aggregate_kernel(const float4* __restrict__ embed_table4,  // [V, 32] float4
                 float4* __restrict__ out4) {              // [B, 32] float4
    const int warp = threadIdx.x >> 5;
    const int lane = threadIdx.x & 31;
    const int b    = blockIdx.x * AGG_WARPS + warp;

    __shared__ int2 s_wo[AGG_WARPS][GCN_K];   // {off4, bitcast(w)}

    // ---- step 1: ONE load resolves everything needed to start gathering ----
    const int2 oc = __ldg(&g_oc[b * GCN_K + lane]);
    s_wo[warp][lane].x = oc.x;
    __syncwarp();

    // ---- step 2: launch the gather pipeline immediately ----
    constexpr int P = 8;
    float4 buf[P];
    #pragma unroll
    for (int i = 0; i < P; i++)
        buf[i] = __ldcg(&embed_table4[s_wo[warp][i].x + lane]);

    // ---- step 3: weight chain resolves under the in-flight gathers ----
    const bool first = oc.y < 0;
    const unsigned mask = __ballot_sync(0xFFFFFFFFu, first);
    float w = 0.0f;
    if (first) {
        int deg = __ldcg(&g_col_deg[oc.y & 0x7FFFFFFF]);  // >= 1 here
        w = rsqrtf((float)deg);
    }
    w *= rsqrtf((float)__popc(mask));         // fold row scale into lane weight
    s_wo[warp][lane].y = __float_as_int(w);
    __syncwarp();

    // ---- step 4: rolling FMA + refill ----
    float4 acc = make_float4(0.f, 0.f, 0.f, 0.f);
    #pragma unroll
    for (int k = 0; k < GCN_K; k++) {
        int2  wo = s_wo[warp][k];
        float wk = __int_as_float(wo.y);
        float4 v = buf[k & (P - 1)];
        acc.x = fmaf(wk, v.x, acc.x);
        acc.y = fmaf(wk, v.y, acc.y);
        acc.z = fmaf(wk, v.z, acc.z);
        acc.w = fmaf(wk, v.w, acc.w);
        if (k + P < GCN_K)
            buf[k & (P - 1)] = __ldcg(&embed_table4[s_wo[warp][k + P].x + lane]);
    }

    out4[b * (GCN_D / 4) + lane] = acc;
}

// ---------------------------------------------------------------------------
extern "C" void kernel_launch(void* const* d_in, const int* in_sizes, int n_in,
                              void* d_out, int out_size) {
    const int*    neigh_cols   = (const int*)d_in[0];
    const int*    unique_ids   = (const int*)d_in[1];
    const float4* embed_table4 = (const float4*)d_in[2];
    float4*       out4         = (float4*)d_out;

    // Zero column degrees via a graph memset node (no dedicated kernel launch).
    void* col_deg_ptr = nullptr;
    cudaGetSymbolAddress(&col_deg_ptr, g_col_deg);
    cudaMemsetAsync(col_deg_ptr, 0, GCN_U * sizeof(int));

    dedupe_degree_kernel<<<GCN_B / 8, 256>>>(neigh_cols, unique_ids);
    aggregate_kernel<<<GCN_B / AGG_WARPS, 32 * AGG_WARPS>>>(embed_table4, out4);
}